// round 7
// baseline (speedup 1.0000x reference)
#include <cuda_runtime.h>

// SNN XORNet, T=20 LIF. Model: runtime ~ issue slots + fma-pipe cycles (issue ceiling
// ~0.6). This round, two bit-identical cuts vs R6:
//  (1) reset-subtract fma2(s,-1,m) -> sub.rn.f32x2 (2-operand: RF-bank rt 3->2 on B300),
//      rnd(m-s) single-rounding either way -> value-identical.
//  (2) store s2 pairs directly as u64 (STG.64 from already-paired regs), killing
//      unpack + float4 staging MOVs.
// T loop fully unrolled (R6 win). 4 elems/thread. Output bit-identical to R1-R6.

#define T_STEPS 20
#define BETA    0.9f
#define THR     1.0f

typedef unsigned long long u64;

__device__ __forceinline__ u64 pack2(float lo, float hi) {
    u64 r; asm("mov.b64 %0, {%1, %2};" : "=l"(r) : "f"(lo), "f"(hi)); return r;
}
__device__ __forceinline__ void unpack2(u64 v, float& lo, float& hi) {
    asm("mov.b64 {%0, %1}, %2;" : "=f"(lo), "=f"(hi) : "l"(v));
}
__device__ __forceinline__ u64 fma2(u64 a, u64 b, u64 c) {
    u64 r; asm("fma.rn.f32x2 %0, %1, %2, %3;" : "=l"(r) : "l"(a), "l"(b), "l"(c)); return r;
}
// packed subtract: rnd(a-b), 2-operand (RF-bank rt=2)
__device__ __forceinline__ u64 sub2(u64 a, u64 b) {
    u64 r; asm("sub.rn.f32x2 %0, %1, %2;" : "=l"(r) : "l"(a), "l"(b)); return r;
}
__device__ __forceinline__ float fset_gt(float a, float b) {
    float r; asm("set.gt.f32.f32 %0, %1, %2;" : "=f"(r) : "f"(a), "f"(b)); return r;
}
__device__ __forceinline__ u64 spike2(u64 m) {
    float lo, hi; unpack2(m, lo, hi);
    return pack2(fset_gt(lo, THR), fset_gt(hi, THR));
}

__global__ __launch_bounds__(128)
void snn_kernel(const float* __restrict__ x,
                const float* __restrict__ w1,   // [4,2]
                const float* __restrict__ w2,   // [1,4]
                float* __restrict__ out,        // [T, B]
                int B)
{
    const int tid = blockIdx.x * blockDim.x + threadIdx.x;
    const int i0  = tid * 4;                    // 4 batch elements = 2 f32x2 pairs
    if (i0 >= B) return;

    float w1v[8];
#pragma unroll
    for (int k = 0; k < 8; k++) w1v[k] = __ldg(w1 + k);
    u64 w2p[4];
#pragma unroll
    for (int k = 0; k < 4; k++) { float w = __ldg(w2 + k); w2p[k] = pack2(w, w); }

    const u64 BETA2 = pack2(BETA, BETA);

    const float4* xv = reinterpret_cast<const float4*>(x + 2 * (size_t)i0);
    float4 xa = xv[0];
    float4 xb = xv[1];
    float xe[4][2] = {{xa.x, xa.y}, {xa.z, xa.w}, {xb.x, xb.y}, {xb.z, xb.w}};

    // cur (timestep-invariant), packed per pair — same scalar math as R1.
    u64 cur2[2][4];
#pragma unroll
    for (int p = 0; p < 2; p++)
#pragma unroll
        for (int h = 0; h < 4; h++) {
            float c0 = fmaf(xe[2*p  ][1], w1v[2*h+1], xe[2*p  ][0] * w1v[2*h]);
            float c1 = fmaf(xe[2*p+1][1], w1v[2*h+1], xe[2*p+1][0] * w1v[2*h]);
            cur2[p][h] = pack2(c0, c1);
        }

    u64 m1[2][4], s1[2][4], m2[2], s2[2];
#pragma unroll
    for (int p = 0; p < 2; p++) {
#pragma unroll
        for (int h = 0; h < 4; h++) { m1[p][h] = 0ull; s1[p][h] = 0ull; }
        m2[p] = 0ull; s2[p] = 0ull;
    }

    float* outp = out + i0;
    const size_t stride = (size_t)B;

#pragma unroll   // full unroll: no loop overhead, const step offsets
    for (int t = 0; t < T_STEPS; t++) {
#pragma unroll
        for (int p = 0; p < 2; p++) {
            u64 acc = 0ull;
#pragma unroll
            for (int h = 0; h < 4; h++) {
                // m = beta*m + cur ; m = m - s_prev (single rounding, identical to fma(s,-1,m))
                m1[p][h] = fma2(BETA2, m1[p][h], cur2[p][h]);
                m1[p][h] = sub2(m1[p][h], s1[p][h]);
                s1[p][h] = spike2(m1[p][h]);           // spk1 = (m > 1)
                acc = fma2(s1[p][h], w2p[h], acc);     // out += spk1*w2 (seq order)
            }
            m2[p] = fma2(BETA2, m2[p], acc);
            m2[p] = sub2(m2[p], s2[p]);
            s2[p] = spike2(m2[p]);
            // direct 64-bit store of the {0.0/1.0, 0.0/1.0} pair — no staging movs
            *reinterpret_cast<u64*>(outp + (size_t)t * stride + 2 * p) = s2[p];
        }
    }
}

extern "C" void kernel_launch(void* const* d_in, const int* in_sizes, int n_in,
                              void* d_out, int out_size)
{
    const float* x  = (const float*)d_in[0];   // [B,2]
    const float* w1 = (const float*)d_in[1];   // [4,2]
    const float* w2 = (const float*)d_in[2];   // [1,4]
    float* out = (float*)d_out;                // [T,B,1]

    const int B = in_sizes[0] / 2;             // 1,048,576
    const int elems_per_thread = 4;
    const int nthreads = (B + elems_per_thread - 1) / elems_per_thread;
    const int block = 128;
    const int grid = (nthreads + block - 1) / block;

    snn_kernel<<<grid, block>>>(x, w1, w2, out, B);
}

// round 8
// speedup vs baseline: 1.5028x; 1.5028x over previous
#include <cuda_runtime.h>

// SNN XORNet, T=20 LIF. R7 regression root-caused: 2x STG.64 at 16B lane stride =
// half-filled sectors + 2x L1 wavefronts (L1 62%, issue 39%). This round: single
// contiguous 128-bit store per step via ulonglong2 {s2[0], s2[1]} (pairs already in
// memory order -> zero staging), keep sub2 (2-operand packed subtract, value-identical
// to fma(s,-1,m)). T loop fully unrolled. Output bit-identical to R1-R7.

#define T_STEPS 20
#define BETA    0.9f
#define THR     1.0f

typedef unsigned long long u64;

__device__ __forceinline__ u64 pack2(float lo, float hi) {
    u64 r; asm("mov.b64 %0, {%1, %2};" : "=l"(r) : "f"(lo), "f"(hi)); return r;
}
__device__ __forceinline__ void unpack2(u64 v, float& lo, float& hi) {
    asm("mov.b64 {%0, %1}, %2;" : "=f"(lo), "=f"(hi) : "l"(v));
}
__device__ __forceinline__ u64 fma2(u64 a, u64 b, u64 c) {
    u64 r; asm("fma.rn.f32x2 %0, %1, %2, %3;" : "=l"(r) : "l"(a), "l"(b), "l"(c)); return r;
}
// packed subtract: rnd(a-b), 2-operand
__device__ __forceinline__ u64 sub2(u64 a, u64 b) {
    u64 r; asm("sub.rn.f32x2 %0, %1, %2;" : "=l"(r) : "l"(a), "l"(b)); return r;
}
__device__ __forceinline__ float fset_gt(float a, float b) {
    float r; asm("set.gt.f32.f32 %0, %1, %2;" : "=f"(r) : "f"(a), "f"(b)); return r;
}
__device__ __forceinline__ u64 spike2(u64 m) {
    float lo, hi; unpack2(m, lo, hi);
    return pack2(fset_gt(lo, THR), fset_gt(hi, THR));
}

__global__ __launch_bounds__(128)
void snn_kernel(const float* __restrict__ x,
                const float* __restrict__ w1,   // [4,2]
                const float* __restrict__ w2,   // [1,4]
                float* __restrict__ out,        // [T, B]
                int B)
{
    const int tid = blockIdx.x * blockDim.x + threadIdx.x;
    const int i0  = tid * 4;                    // 4 batch elements = 2 f32x2 pairs
    if (i0 >= B) return;

    float w1v[8];
#pragma unroll
    for (int k = 0; k < 8; k++) w1v[k] = __ldg(w1 + k);
    u64 w2p[4];
#pragma unroll
    for (int k = 0; k < 4; k++) { float w = __ldg(w2 + k); w2p[k] = pack2(w, w); }

    const u64 BETA2 = pack2(BETA, BETA);

    const float4* xv = reinterpret_cast<const float4*>(x + 2 * (size_t)i0);
    float4 xa = xv[0];
    float4 xb = xv[1];
    float xe[4][2] = {{xa.x, xa.y}, {xa.z, xa.w}, {xb.x, xb.y}, {xb.z, xb.w}};

    // cur (timestep-invariant), packed per pair — same scalar math as R1.
    u64 cur2[2][4];
#pragma unroll
    for (int p = 0; p < 2; p++)
#pragma unroll
        for (int h = 0; h < 4; h++) {
            float c0 = fmaf(xe[2*p  ][1], w1v[2*h+1], xe[2*p  ][0] * w1v[2*h]);
            float c1 = fmaf(xe[2*p+1][1], w1v[2*h+1], xe[2*p+1][0] * w1v[2*h]);
            cur2[p][h] = pack2(c0, c1);
        }

    u64 m1[2][4], s1[2][4], m2[2], s2[2];
#pragma unroll
    for (int p = 0; p < 2; p++) {
#pragma unroll
        for (int h = 0; h < 4; h++) { m1[p][h] = 0ull; s1[p][h] = 0ull; }
        m2[p] = 0ull; s2[p] = 0ull;
    }

    float* outp = out + i0;
    const size_t stride = (size_t)B;

#pragma unroll   // full unroll: no loop overhead, const step offsets
    for (int t = 0; t < T_STEPS; t++) {
#pragma unroll
        for (int p = 0; p < 2; p++) {
            u64 acc = 0ull;
#pragma unroll
            for (int h = 0; h < 4; h++) {
                // m = beta*m + cur ; m = m - s_prev (single rounding == fma(s,-1,m))
                m1[p][h] = fma2(BETA2, m1[p][h], cur2[p][h]);
                m1[p][h] = sub2(m1[p][h], s1[p][h]);
                s1[p][h] = spike2(m1[p][h]);           // spk1 = (m > 1)
                acc = fma2(s1[p][h], w2p[h], acc);     // out += spk1*w2 (seq order)
            }
            m2[p] = fma2(BETA2, m2[p], acc);
            m2[p] = sub2(m2[p], s2[p]);
            s2[p] = spike2(m2[p]);
        }
        // one fully-coalesced 128-bit store: pairs already in memory order
        ulonglong2 ov; ov.x = s2[0]; ov.y = s2[1];
        *reinterpret_cast<ulonglong2*>(outp + (size_t)t * stride) = ov;
    }
}

extern "C" void kernel_launch(void* const* d_in, const int* in_sizes, int n_in,
                              void* d_out, int out_size)
{
    const float* x  = (const float*)d_in[0];   // [B,2]
    const float* w1 = (const float*)d_in[1];   // [4,2]
    const float* w2 = (const float*)d_in[2];   // [1,4]
    float* out = (float*)d_out;                // [T,B,1]

    const int B = in_sizes[0] / 2;             // 1,048,576
    const int elems_per_thread = 4;
    const int nthreads = (B + elems_per_thread - 1) / elems_per_thread;
    const int block = 128;
    const int grid = (nthreads + block - 1) / block;

    snn_kernel<<<grid, block>>>(x, w1, w2, out, B);
}